// round 1
// baseline (speedup 1.0000x reference)
#include <cuda_runtime.h>
#include <stdint.h>

#define NUM_CLASSES 32000
#define C4 (NUM_CLASSES / 4)
#define ALPHA 0.95f
#define THREADS 512

// Flag: 1 if labels buffer is int64, 0 if int32. Set by detect_kernel.
__device__ int g_lab_is_64 = 0;

// Decide label dtype by interpreting the first n/2 entries as uint64.
// - If truly int64: these are n/2 real labels, all in [0, 32000) -> flag=1.
// - If truly int32: each uint64 read combines two int32 labels; it is only
//   < 32000 if the odd-position label is exactly 0. Probability all n/2
//   pairs satisfy that is ~(1/32000)^(n/2) ~ 0 -> flag=0.
// Reading n/2 * 8 bytes stays within bounds for BOTH layouts.
__global__ void detect_kernel(const unsigned long long* __restrict__ labels, int n_half) {
    __shared__ int bad;
    if (threadIdx.x == 0) bad = 0;
    __syncthreads();
    int local_bad = 0;
    for (int i = threadIdx.x; i < n_half; i += blockDim.x) {
        if (labels[i] >= (unsigned long long)NUM_CLASSES) local_bad = 1;
    }
    if (local_bad) bad = 1;
    __syncthreads();
    if (threadIdx.x == 0) g_lab_is_64 = (bad == 0) ? 1 : 0;
}

__global__ __launch_bounds__(THREADS)
void distill_kernel(const float* __restrict__ x,
                    const void*  __restrict__ labels,
                    float*       __restrict__ out) {
    const int row = blockIdx.x;
    const int tid = threadIdx.x;

    const float4* __restrict__ xr = reinterpret_cast<const float4*>(x + (size_t)row * NUM_CLASSES);
    float4*       __restrict__ orow = reinterpret_cast<float4*>(out + (size_t)row * NUM_CLASSES);

    // ---- Phase 1: row sum (float4 vectorized) ----
    float sum = 0.0f;
    #pragma unroll 4
    for (int i = tid; i < C4; i += THREADS) {
        float4 v = xr[i];
        sum += (v.x + v.y) + (v.z + v.w);
    }

    // Block reduce: warp shuffle, then first warp folds the 16 partials.
    __shared__ float warp_sums[THREADS / 32];
    __shared__ float s_S;
    #pragma unroll
    for (int off = 16; off > 0; off >>= 1)
        sum += __shfl_down_sync(0xffffffffu, sum, off);
    const int lane = tid & 31;
    const int wid  = tid >> 5;
    if (lane == 0) warp_sums[wid] = sum;
    __syncthreads();
    if (wid == 0) {
        float v = (lane < THREADS / 32) ? warp_sums[lane] : 0.0f;
        #pragma unroll
        for (int off = 8; off > 0; off >>= 1)
            v += __shfl_down_sync(0xffffffffu, v, off);
        if (lane == 0) s_S = v;
    }
    __syncthreads();

    const float S = s_S;

    // Label (dtype chosen at runtime via detection flag).
    int lab;
    if (g_lab_is_64) lab = (int)(((const long long*)labels)[row]);
    else             lab = ((const int*)labels)[row];

    const float t = __ldg(x + (size_t)row * NUM_CLASSES + lab);
    const float s = ALPHA / (1.0f + S - 2.0f * t);
    const float corr = 1.0f - s * S;

    const int lab4 = lab >> 2;
    const int labc = lab & 3;

    // ---- Phase 2: scale + fused label correction (re-read hits L1/L2) ----
    #pragma unroll 4
    for (int i = tid; i < C4; i += THREADS) {
        float4 v = xr[i];
        float4 o;
        o.x = s * v.x;
        o.y = s * v.y;
        o.z = s * v.z;
        o.w = s * v.w;
        if (i == lab4) {
            reinterpret_cast<float*>(&o)[labc] += corr;
        }
        orow[i] = o;
    }
}

extern "C" void kernel_launch(void* const* d_in, const int* in_sizes, int n_in,
                              void* d_out, int out_size) {
    const float* teacher_logits = (const float*)d_in[0];
    const void*  true_labels    = d_in[1];
    float* out = (float*)d_out;

    const int batch = in_sizes[1];   // 4096 rows (label count)

    detect_kernel<<<1, 256>>>((const unsigned long long*)true_labels, batch / 2);
    distill_kernel<<<batch, THREADS>>>(teacher_logits, true_labels, out);
}